// round 6
// baseline (speedup 1.0000x reference)
#include <cuda_runtime.h>
#include <cuda_bf16.h>

// R5: occupancy split — 2 threads per query row (each owns 32 of 64 head dims).
// Halves per-thread register state (230 -> ~110 regs) so 2 CTAs x 256 thr
// = 16 warps/SM (2x R4). One shfl.xor(1) per key combines the half-dots.
// Keeps f32x2 packed math + 2-key unroll from R4 (380us baseline).

constexpr int B = 64;
constexpr int S = 1024;
constexpr int D = 64;
constexpr int H = D / 2;       // 32 floats per thread half
constexpr int TPB = 256;       // threads per block
constexpr int QPB = TPB / 2;   // 128 query rows per block
constexpr int KT  = 64;        // key tile

using u64 = unsigned long long;

__device__ __forceinline__ u64 ffma2(u64 a, u64 b, u64 c) {
    u64 d;
    asm("fma.rn.f32x2 %0, %1, %2, %3;" : "=l"(d) : "l"(a), "l"(b), "l"(c));
    return d;
}
__device__ __forceinline__ u64 fmul2(u64 a, u64 b) {
    u64 d;
    asm("mul.rn.f32x2 %0, %1, %2;" : "=l"(d) : "l"(a), "l"(b));
    return d;
}
__device__ __forceinline__ u64 fadd2(u64 a, u64 b) {
    u64 d;
    asm("add.rn.f32x2 %0, %1, %2;" : "=l"(d) : "l"(a), "l"(b));
    return d;
}
__device__ __forceinline__ u64 pack2(float lo, float hi) {
    u64 r;
    asm("mov.b64 %0, {%1, %2};" : "=l"(r) : "f"(lo), "f"(hi));
    return r;
}
__device__ __forceinline__ void unpack2(u64 v, float& lo, float& hi) {
    asm("mov.b64 {%0, %1}, %2;" : "=f"(lo), "=f"(hi) : "l"(v));
}

// Half-row dot: 32 floats = 4 x ulonglong2 loads, 4 packed accumulators.
__device__ __forceinline__ float dot_half(const u64* q2, const float* krow_half) {
    const ulonglong2* kr = reinterpret_cast<const ulonglong2*>(krow_half);
    u64 a0 = 0, a1 = 0, a2 = 0, a3 = 0;
    #pragma unroll
    for (int i = 0; i < H / 8; i++) {       // 4 iters
        ulonglong2 kA = kr[2*i];
        ulonglong2 kB = kr[2*i+1];
        a0 = ffma2(q2[4*i+0], kA.x, a0);
        a1 = ffma2(q2[4*i+1], kA.y, a1);
        a2 = ffma2(q2[4*i+2], kB.x, a2);
        a3 = ffma2(q2[4*i+3], kB.y, a3);
    }
    u64 sp = fadd2(fadd2(a0, a1), fadd2(a2, a3));
    float slo, shi;
    unpack2(sp, slo, shi);
    return slo + shi;
}

__global__ __launch_bounds__(TPB, 2)
void attn_fp32x2_split(const float* __restrict__ Q,
                       const float* __restrict__ K,
                       const float* __restrict__ V,
                       const int* __restrict__ lens,
                       float* __restrict__ O)
{
    __shared__ float Ks[KT * D];
    __shared__ float Vs[KT * D];

    const int b    = blockIdx.y;
    const int t    = threadIdx.x;
    const int qrow = blockIdx.x * QPB + (t >> 1);
    const int half = t & 1;                 // which 32-dim half this thread owns
    const int len  = lens[b];

    float* ohalf = O + ((size_t)b * S + qrow) * D + half * H;

    if (len <= 0) {
        float4 z = make_float4(0.f, 0.f, 0.f, 0.f);
        float4* o4 = reinterpret_cast<float4*>(ohalf);
        #pragma unroll
        for (int i = 0; i < H / 4; i++) o4[i] = z;
        return;
    }

    // This thread's half of the query row, packed, pre-scaled by 1/sqrt(D).
    u64 q2[H / 2];
    {
        const u64 scale2 = pack2(0.125f, 0.125f);
        const ulonglong2* qg = reinterpret_cast<const ulonglong2*>(
            Q + ((size_t)b * S + qrow) * D + half * H);
        #pragma unroll
        for (int i = 0; i < H / 4; i++) {
            ulonglong2 v = qg[i];
            q2[2*i+0] = fmul2(v.x, scale2);
            q2[2*i+1] = fmul2(v.y, scale2);
        }
    }

    u64 o2[H / 2];                          // 16 u64 = 32 floats
    #pragma unroll
    for (int i = 0; i < H / 2; i++) o2[i] = 0;
    float m = -1e30f;
    float l = 0.f;

    for (int jt = 0; jt < len; jt += KT) {
        __syncthreads();
        {
            // 2 tiles x 4096 floats; 256 threads x 8 float4 each, coalesced.
            const float4* Kg = reinterpret_cast<const float4*>(K + ((size_t)b * S + jt) * D);
            const float4* Vg = reinterpret_cast<const float4*>(V + ((size_t)b * S + jt) * D);
            float4* Ks4 = reinterpret_cast<float4*>(Ks);
            float4* Vs4 = reinterpret_cast<float4*>(Vs);
            #pragma unroll
            for (int i = t; i < KT * D / 4; i += TPB) {
                Ks4[i] = Kg[i];
                Vs4[i] = Vg[i];
            }
        }
        __syncthreads();

        const int jend = min(KT, len - jt);
        int j = 0;
        for (; j + 1 < jend; j += 2) {
            // Two independent half-dots, then pairwise combine via shfl.xor(1).
            float ha = dot_half(q2, Ks + (j + 0) * D + half * H);
            float hb = dot_half(q2, Ks + (j + 1) * D + half * H);
            float sa = ha + __shfl_xor_sync(0xFFFFFFFFu, ha, 1);
            float sb = hb + __shfl_xor_sync(0xFFFFFFFFu, hb, 1);

            float smax = fmaxf(sa, sb);
            if (smax > m) {
                float corr = __expf(m - smax);   // exp(-inf)=0 on first pair
                m = smax;
                l *= corr;
                u64 corr2 = pack2(corr, corr);
                #pragma unroll
                for (int i = 0; i < H / 2; i++) o2[i] = fmul2(o2[i], corr2);
            }

            float pa = __expf(sa - m);
            float pb = __expf(sb - m);
            l += pa + pb;
            u64 pa2 = pack2(pa, pa);
            u64 pb2 = pack2(pb, pb);

            const ulonglong2* va = reinterpret_cast<const ulonglong2*>(Vs + (j + 0) * D + half * H);
            const ulonglong2* vb = reinterpret_cast<const ulonglong2*>(Vs + (j + 1) * D + half * H);
            #pragma unroll
            for (int i = 0; i < H / 4; i++) {    // 8 iters of 16B
                ulonglong2 tva = va[i];
                ulonglong2 tvb = vb[i];
                o2[2*i+0] = ffma2(pa2, tva.x, o2[2*i+0]);
                o2[2*i+1] = ffma2(pa2, tva.y, o2[2*i+1]);
                o2[2*i+0] = ffma2(pb2, tvb.x, o2[2*i+0]);
                o2[2*i+1] = ffma2(pb2, tvb.y, o2[2*i+1]);
            }
        }
        if (j < jend) {                          // odd tail key
            float hs = dot_half(q2, Ks + j * D + half * H);
            float s  = hs + __shfl_xor_sync(0xFFFFFFFFu, hs, 1);
            if (s > m) {
                float corr = __expf(m - s);
                m = s;
                l *= corr;
                u64 corr2 = pack2(corr, corr);
                #pragma unroll
                for (int i = 0; i < H / 2; i++) o2[i] = fmul2(o2[i], corr2);
            }
            float p = __expf(s - m);
            l += p;
            u64 p2 = pack2(p, p);
            const ulonglong2* vr = reinterpret_cast<const ulonglong2*>(Vs + j * D + half * H);
            #pragma unroll
            for (int i = 0; i < H / 4; i++) {
                ulonglong2 v = vr[i];
                o2[2*i+0] = ffma2(p2, v.x, o2[2*i+0]);
                o2[2*i+1] = ffma2(p2, v.y, o2[2*i+1]);
            }
        }
    }

    const float inv = 1.0f / l;                  // identical in both pair threads
    const u64 inv2 = pack2(inv, inv);
    ulonglong2* og = reinterpret_cast<ulonglong2*>(ohalf);
    #pragma unroll
    for (int i = 0; i < H / 4; i++) {
        ulonglong2 v;
        v.x = fmul2(o2[2*i+0], inv2);
        v.y = fmul2(o2[2*i+1], inv2);
        og[i] = v;
    }
}

extern "C" void kernel_launch(void* const* d_in, const int* in_sizes, int n_in,
                              void* d_out, int out_size)
{
    const float* Qp = (const float*)d_in[0];
    const float* Kp = (const float*)d_in[1];
    const float* Vp = (const float*)d_in[2];
    const int*   Lp = (const int*)d_in[3];
    float*       Op = (float*)d_out;

    dim3 grid(S / QPB, B);
    attn_fp32x2_split<<<grid, TPB>>>(Qp, Kp, Vp, Lp, Op);
}

// round 8
// speedup vs baseline: 3.5003x; 3.5003x over previous
#include <cuda_runtime.h>
#include <cstdint>

// R7: identical resubmission of the R6 tensor-core kernel (R6 bench died to
// container infra failure; kernel never executed). Static re-audit done on
// fragment permutation + smem bank padding; no functional changes.
//
// mma.sync.m16n8k8 tf32:
//   QK^T via 3xTF32 split (error ~1e-7), PV via tf32-rounded P x split V
//   (error ~2.4e-4 global, threshold 1e-3).
// CTA: 4 warps x 16 q-rows = 64 rows; K/V tiles of 32 keys in smem (hi/lo,
// padded strides 68/72 words -> conflict-free B-fragment LDS).

constexpr int B    = 64;
constexpr int S    = 1024;
constexpr int D    = 64;
constexpr int TPB  = 128;   // 4 warps
constexpr int QT   = 64;    // q rows per CTA
constexpr int KT   = 32;    // keys per smem tile
constexpr int KSTR = 68;    // K smem row stride (words)
constexpr int VSTR = 72;    // V smem row stride (words)

__device__ __forceinline__ uint32_t tf32b(float x) {
    uint32_t u;
    asm("cvt.rna.tf32.f32 %0, %1;" : "=r"(u) : "f"(x));
    return u;
}

__device__ __forceinline__ void mma8(float c[4], const uint32_t a[4],
                                     uint32_t b0, uint32_t b1) {
    asm("mma.sync.aligned.m16n8k8.row.col.f32.tf32.tf32.f32 "
        "{%0,%1,%2,%3}, {%4,%5,%6,%7}, {%8,%9}, {%0,%1,%2,%3};"
        : "+f"(c[0]), "+f"(c[1]), "+f"(c[2]), "+f"(c[3])
        : "r"(a[0]), "r"(a[1]), "r"(a[2]), "r"(a[3]), "r"(b0), "r"(b1));
}

__global__ __launch_bounds__(TPB)
void attn_tf32_mma(const float* __restrict__ Q,
                   const float* __restrict__ K,
                   const float* __restrict__ V,
                   const int* __restrict__ lens,
                   float* __restrict__ O)
{
    __shared__ float Khi[KT][KSTR], Klo[KT][KSTR];
    __shared__ float Vhi[KT][VSTR], Vlo[KT][VSTR];

    const int b    = blockIdx.y;
    const int len  = lens[b];
    const int tid  = threadIdx.x;
    const int warp = tid >> 5;
    const int lane = tid & 31;
    const int quad = lane & 3;     // threadID within quad group
    const int qr   = lane >> 2;    // group id 0..7

    const int qbase = blockIdx.x * QT;
    float* Ob = O + ((size_t)b * S + qbase) * D;

    if (len <= 0) {
        float4 z = make_float4(0.f, 0.f, 0.f, 0.f);
        float4* o4 = reinterpret_cast<float4*>(Ob);
        for (int i = tid; i < QT * D / 4; i += TPB) o4[i] = z;
        return;
    }

    const float* Qb = Q + ((size_t)b * S + qbase) * D;
    const int r0 = warp * 16 + qr;   // local q rows this thread owns
    const int r1 = r0 + 8;

    // Q A-fragments, hi/lo split, pre-scaled by 1/sqrt(D)=0.125 (exact).
    uint32_t qhi[8][4], qlo[8][4];
    #pragma unroll
    for (int kb = 0; kb < 8; kb++) {
        int d0 = kb * 8 + quad, d1 = d0 + 4;
        float v[4];
        v[0] = Qb[r0 * D + d0] * 0.125f;
        v[1] = Qb[r1 * D + d0] * 0.125f;
        v[2] = Qb[r0 * D + d1] * 0.125f;
        v[3] = Qb[r1 * D + d1] * 0.125f;
        #pragma unroll
        for (int i = 0; i < 4; i++) {
            uint32_t h = tf32b(v[i]);
            qhi[kb][i] = h;
            qlo[kb][i] = tf32b(v[i] - __uint_as_float(h));
        }
    }

    float Oa[8][4];
    #pragma unroll
    for (int nt = 0; nt < 8; nt++)
        #pragma unroll
        for (int i = 0; i < 4; i++) Oa[nt][i] = 0.f;
    float m0 = -1e30f, m1 = -1e30f, l0 = 0.f, l1 = 0.f;

    for (int jt = 0; jt < len; jt += KT) {
        __syncthreads();
        {   // cooperative tile load + hi/lo split (coalesced LDG.128)
            const float4* Kg = reinterpret_cast<const float4*>(K + ((size_t)b * S + jt) * D);
            const float4* Vg = reinterpret_cast<const float4*>(V + ((size_t)b * S + jt) * D);
            #pragma unroll
            for (int it = 0; it < (KT * D / 4) / TPB; it++) {   // 4 iters
                int i   = tid + it * TPB;
                int key = i >> 4;
                int dw  = (i & 15) * 4;
                float4 kv = Kg[i];
                float4 h4, s4;
                h4.x = __uint_as_float(tf32b(kv.x)); s4.x = __uint_as_float(tf32b(kv.x - h4.x));
                h4.y = __uint_as_float(tf32b(kv.y)); s4.y = __uint_as_float(tf32b(kv.y - h4.y));
                h4.z = __uint_as_float(tf32b(kv.z)); s4.z = __uint_as_float(tf32b(kv.z - h4.z));
                h4.w = __uint_as_float(tf32b(kv.w)); s4.w = __uint_as_float(tf32b(kv.w - h4.w));
                *reinterpret_cast<float4*>(&Khi[key][dw]) = h4;
                *reinterpret_cast<float4*>(&Klo[key][dw]) = s4;
                float4 vv = Vg[i];
                h4.x = __uint_as_float(tf32b(vv.x)); s4.x = __uint_as_float(tf32b(vv.x - h4.x));
                h4.y = __uint_as_float(tf32b(vv.y)); s4.y = __uint_as_float(tf32b(vv.y - h4.y));
                h4.z = __uint_as_float(tf32b(vv.z)); s4.z = __uint_as_float(tf32b(vv.z - h4.z));
                h4.w = __uint_as_float(tf32b(vv.w)); s4.w = __uint_as_float(tf32b(vv.w - h4.w));
                *reinterpret_cast<float4*>(&Vhi[key][dw]) = h4;
                *reinterpret_cast<float4*>(&Vlo[key][dw]) = s4;
            }
        }
        __syncthreads();

        const bool tail = (jt + KT > len);

        // S = Q K^T for 32 keys (4 n-tiles of 8), 3xTF32.
        float P[4][4];
        #pragma unroll
        for (int nt = 0; nt < 4; nt++) {
            float c[4] = {0.f, 0.f, 0.f, 0.f};
            #pragma unroll
            for (int kb = 0; kb < 8; kb++) {
                int kd = kb * 8 + quad;
                int kk = nt * 8 + qr;
                uint32_t bh0 = __float_as_uint(Khi[kk][kd]);
                uint32_t bh1 = __float_as_uint(Khi[kk][kd + 4]);
                uint32_t bl0 = __float_as_uint(Klo[kk][kd]);
                uint32_t bl1 = __float_as_uint(Klo[kk][kd + 4]);
                mma8(c, qhi[kb], bh0, bh1);
                mma8(c, qhi[kb], bl0, bl1);
                mma8(c, qlo[kb], bh0, bh1);
            }
            if (tail) {   // mask keys >= len (exp(-1e30 - m) == 0)
                int k0 = jt + nt * 8 + 2 * quad;
                if (k0     >= len) { c[0] = -1e30f; c[2] = -1e30f; }
                if (k0 + 1 >= len) { c[1] = -1e30f; c[3] = -1e30f; }
            }
            P[nt][0] = c[0]; P[nt][1] = c[1]; P[nt][2] = c[2]; P[nt][3] = c[3];
        }

        // Online softmax (rows r0 from regs 0,1; rows r1 from regs 2,3).
        float tm0 = fmaxf(fmaxf(P[0][0], P[0][1]), fmaxf(P[1][0], P[1][1]));
        tm0 = fmaxf(tm0, fmaxf(fmaxf(P[2][0], P[2][1]), fmaxf(P[3][0], P[3][1])));
        float tm1 = fmaxf(fmaxf(P[0][2], P[0][3]), fmaxf(P[1][2], P[1][3]));
        tm1 = fmaxf(tm1, fmaxf(fmaxf(P[2][2], P[2][3]), fmaxf(P[3][2], P[3][3])));
        tm0 = fmaxf(tm0, __shfl_xor_sync(0xFFFFFFFFu, tm0, 1));
        tm0 = fmaxf(tm0, __shfl_xor_sync(0xFFFFFFFFu, tm0, 2));
        tm1 = fmaxf(tm1, __shfl_xor_sync(0xFFFFFFFFu, tm1, 1));
        tm1 = fmaxf(tm1, __shfl_xor_sync(0xFFFFFFFFu, tm1, 2));
        float mn0 = fmaxf(m0, tm0), mn1 = fmaxf(m1, tm1);
        float c0 = __expf(m0 - mn0), c1 = __expf(m1 - mn1);
        m0 = mn0; m1 = mn1;
        l0 *= c0; l1 *= c1;
        #pragma unroll
        for (int nt = 0; nt < 8; nt++) {
            Oa[nt][0] *= c0; Oa[nt][1] *= c0;
            Oa[nt][2] *= c1; Oa[nt][3] *= c1;
        }
        #pragma unroll
        for (int nt = 0; nt < 4; nt++) {
            float p0 = __expf(P[nt][0] - m0), p1 = __expf(P[nt][1] - m0);
            float p2 = __expf(P[nt][2] - m1), p3 = __expf(P[nt][3] - m1);
            l0 += p0 + p1;
            l1 += p2 + p3;
            P[nt][0] = __uint_as_float(tf32b(p0));
            P[nt][1] = __uint_as_float(tf32b(p1));
            P[nt][2] = __uint_as_float(tf32b(p2));
            P[nt][3] = __uint_as_float(tf32b(p3));
        }

        // P (C-layout) -> A-fragments via quad shfl, then PV with split V.
        #pragma unroll
        for (int kb2 = 0; kb2 < 4; kb2++) {
            int base = lane & ~3;
            int s0 = base + (quad >> 1);        // source for key col = quad
            int s1 = base + 2 + (quad >> 1);    // source for key col = quad+4
            float u00 = __shfl_sync(0xFFFFFFFFu, P[kb2][0], s0);
            float u01 = __shfl_sync(0xFFFFFFFFu, P[kb2][1], s0);
            float u10 = __shfl_sync(0xFFFFFFFFu, P[kb2][0], s1);
            float u11 = __shfl_sync(0xFFFFFFFFu, P[kb2][1], s1);
            float w00 = __shfl_sync(0xFFFFFFFFu, P[kb2][2], s0);
            float w01 = __shfl_sync(0xFFFFFFFFu, P[kb2][3], s0);
            float w10 = __shfl_sync(0xFFFFFFFFu, P[kb2][2], s1);
            float w11 = __shfl_sync(0xFFFFFFFFu, P[kb2][3], s1);
            bool odd = (quad & 1);
            uint32_t a[4];
            a[0] = __float_as_uint(odd ? u01 : u00);   // (r0, key quad)
            a[1] = __float_as_uint(odd ? w01 : w00);   // (r1, key quad)
            a[2] = __float_as_uint(odd ? u11 : u10);   // (r0, key quad+4)
            a[3] = __float_as_uint(odd ? w11 : w10);   // (r1, key quad+4)
            #pragma unroll
            for (int nt = 0; nt < 8; nt++) {
                int vk = kb2 * 8 + quad;
                int vd = nt * 8 + qr;
                uint32_t bh0 = __float_as_uint(Vhi[vk][vd]);
                uint32_t bh1 = __float_as_uint(Vhi[vk + 4][vd]);
                uint32_t bl0 = __float_as_uint(Vlo[vk][vd]);
                uint32_t bl1 = __float_as_uint(Vlo[vk + 4][vd]);
                mma8(Oa[nt], a, bh0, bh1);
                mma8(Oa[nt], a, bl0, bl1);
            }
        }
    }

    // Finalize: reduce l across quad, normalize, store.
    l0 += __shfl_xor_sync(0xFFFFFFFFu, l0, 1);
    l0 += __shfl_xor_sync(0xFFFFFFFFu, l0, 2);
    l1 += __shfl_xor_sync(0xFFFFFFFFu, l1, 1);
    l1 += __shfl_xor_sync(0xFFFFFFFFu, l1, 2);
    float i0 = 1.f / l0, i1 = 1.f / l1;
    #pragma unroll
    for (int nt = 0; nt < 8; nt++) {
        int d = nt * 8 + 2 * quad;
        float2 t0 = make_float2(Oa[nt][0] * i0, Oa[nt][1] * i0);
        float2 t1 = make_float2(Oa[nt][2] * i1, Oa[nt][3] * i1);
        *reinterpret_cast<float2*>(&Ob[r0 * D + d]) = t0;
        *reinterpret_cast<float2*>(&Ob[r1 * D + d]) = t1;
    }
}

extern "C" void kernel_launch(void* const* d_in, const int* in_sizes, int n_in,
                              void* d_out, int out_size)
{
    const float* Qp = (const float*)d_in[0];
    const float* Kp = (const float*)d_in[1];
    const float* Vp = (const float*)d_in[2];
    const int*   Lp = (const int*)d_in[3];
    float*       Op = (float*)d_out;

    dim3 grid(S / QT, B);
    attn_tf32_mma<<<grid, TPB>>>(Qp, Kp, Vp, Lp, Op);
}